// round 5
// baseline (speedup 1.0000x reference)
#include <cuda_runtime.h>
#include <cuda_bf16.h>
#include <math.h>
#include <stdint.h>

#define Bc  2
#define Ic  2048
#define Mc  2048
#define Dc  1024
#define Hc  16
#define Dhc 64
#define BHc 32   // Bc*Hc

// ---------------- scratch (static device globals; no allocs) ----------------
__device__ __nv_bfloat16 g_Qh[BHc * (size_t)Ic * Dhc];
__device__ __nv_bfloat16 g_Ql[BHc * (size_t)Ic * Dhc];
__device__ __nv_bfloat16 g_Kh[BHc * (size_t)Mc * Dhc];
__device__ __nv_bfloat16 g_Kl[BHc * (size_t)Mc * Dhc];
__device__ __nv_bfloat16 g_Vh[BHc * (size_t)Mc * Dhc];
__device__ __nv_bfloat16 g_Vl[BHc * (size_t)Mc * Dhc];
__device__ float  g_O[Bc * (size_t)Ic * Dc];     // [B,I,D] (pre-Wo)
__device__ float2 g_stats[BHc * Ic];             // (rowmax, 1/rowsum)

// ======================= mma.sync helpers (sm_80+ path) =====================
__device__ __forceinline__ uint32_t smem_u32(const void* p) {
    return (uint32_t)__cvta_generic_to_shared(p);
}
__device__ __forceinline__ void ldsm4(uint32_t addr, uint32_t* r) {
    asm volatile("ldmatrix.sync.aligned.m8n8.x4.shared.b16 {%0,%1,%2,%3}, [%4];"
                 : "=r"(r[0]), "=r"(r[1]), "=r"(r[2]), "=r"(r[3]) : "r"(addr));
}
__device__ __forceinline__ void ldsm4t(uint32_t addr, uint32_t* r) {
    asm volatile("ldmatrix.sync.aligned.m8n8.x4.trans.shared.b16 {%0,%1,%2,%3}, [%4];"
                 : "=r"(r[0]), "=r"(r[1]), "=r"(r[2]), "=r"(r[3]) : "r"(addr));
}
__device__ __forceinline__ void mma16816(float* c, const uint32_t* a, const uint32_t* b) {
    asm volatile(
        "mma.sync.aligned.m16n8k16.row.col.f32.bf16.bf16.f32 "
        "{%0,%1,%2,%3}, {%4,%5,%6,%7}, {%8,%9}, {%0,%1,%2,%3};"
        : "+f"(c[0]), "+f"(c[1]), "+f"(c[2]), "+f"(c[3])
        : "r"(a[0]), "r"(a[1]), "r"(a[2]), "r"(a[3]), "r"(b[0]), "r"(b[1]));
}
__device__ __forceinline__ void cvt_split(float x, float y,
                                          __nv_bfloat162& h, __nv_bfloat162& l) {
    __nv_bfloat16 hx = __float2bfloat16(x);
    __nv_bfloat16 hy = __float2bfloat16(y);
    h.x = hx; h.y = hy;
    l.x = __float2bfloat16(x - __bfloat162float(hx));
    l.y = __float2bfloat16(y - __bfloat162float(hy));
}
// fast exp on the FMA pipe (no MUFU)
__device__ __forceinline__ float fexp(float x) {
    float y = fmaxf(x * 1.4426950408889634f, -126.0f);
    float z = y + 12582912.0f;
    int   n = __float_as_int(z) - 0x4B400000;
    float r = y - (z - 12582912.0f);
    float w = r * 0.69314718055994531f;
    float p = fmaf(w, 1.3888889e-3f, 8.3333333e-3f);
    p = fmaf(w, p, 4.1666667e-2f);
    p = fmaf(w, p, 1.6666667e-1f);
    p = fmaf(w, p, 0.5f);
    p = fmaf(w, p, 1.0f);
    p = fmaf(w, p, 1.0f);
    return p * __int_as_float((n + 127) << 23);
}
__device__ __forceinline__ void cp16(uint32_t dst, const void* src) {
    asm volatile("cp.async.ca.shared.global [%0], [%1], 16;" :: "r"(dst), "l"(src));
}
#define CP_COMMIT() asm volatile("cp.async.commit_group;" ::: "memory")
#define CP_WAIT0()  asm volatile("cp.async.wait_group 0;" ::: "memory")

// ============ bf16-split tensor-core GEMM: C[4096x1024] = A @ W =============
#define BKg     32
#define NCHUNK  (Dc / BKg)          // 32
#define A_PITCH 80
#define B_PITCH 272
#define A_BUF   (128 * A_PITCH)
#define B_BUF   (BKg * B_PITCH)
#define OFF_AH  0
#define OFF_AL  (2 * A_BUF)
#define OFF_BH  (4 * A_BUF)
#define OFF_BL  (OFF_BH + 2 * B_BUF)
#define SMEM_GEMM (OFF_BL + 2 * B_BUF) // 75776

__device__ __forceinline__ void gemm_sm(const float* __restrict__ A,
                                        const float* __restrict__ W,
                                        float* __restrict__ Cout,
                                        __nv_bfloat16* __restrict__ Ch,
                                        __nv_bfloat16* __restrict__ Cl,
                                        float scale, bool splitout) {
    extern __shared__ char sm[];
    const uint32_t smb = smem_u32(sm);

    const int tid  = threadIdx.x;
    const int wid  = tid >> 5;
    const int lane = tid & 31;
    const int wr   = wid & 1;
    const int wc   = wid >> 1;
    const int row0 = blockIdx.y * 128;
    const int col0 = blockIdx.x * 128;

    int arow[4], ac4[4], wrow[4], wc4[4];
#pragma unroll
    for (int t = 0; t < 4; t++) {
        const int fi = tid + t * 256;
        arow[t] = fi >> 3;  ac4[t] = (fi & 7) * 4;
        wrow[t] = fi >> 5;  wc4[t] = (fi & 31) * 4;
    }

    float4 ra[4], rw[4];
    auto ld_chunk = [&](int k0) {
#pragma unroll
        for (int t = 0; t < 4; t++) {
            ra[t] = *(const float4*)(A + (size_t)(row0 + arow[t]) * Dc + k0 + ac4[t]);
            rw[t] = *(const float4*)(W + (size_t)(k0 + wrow[t]) * Dc + col0 + wc4[t]);
        }
    };
    auto st_chunk = [&](int buf) {
#pragma unroll
        for (int t = 0; t < 4; t++) {
            __nv_bfloat162 h0, l0, h1, l1;
            cvt_split(ra[t].x, ra[t].y, h0, l0);
            cvt_split(ra[t].z, ra[t].w, h1, l1);
            const int ao = buf * A_BUF + arow[t] * A_PITCH + ac4[t] * 2;
            *(__nv_bfloat162*)(sm + OFF_AH + ao)     = h0;
            *(__nv_bfloat162*)(sm + OFF_AH + ao + 4) = h1;
            *(__nv_bfloat162*)(sm + OFF_AL + ao)     = l0;
            *(__nv_bfloat162*)(sm + OFF_AL + ao + 4) = l1;
            cvt_split(rw[t].x, rw[t].y, h0, l0);
            cvt_split(rw[t].z, rw[t].w, h1, l1);
            const int bo = buf * B_BUF + wrow[t] * B_PITCH + wc4[t] * 2;
            *(__nv_bfloat162*)(sm + OFF_BH + bo)     = h0;
            *(__nv_bfloat162*)(sm + OFF_BH + bo + 4) = h1;
            *(__nv_bfloat162*)(sm + OFF_BL + bo)     = l0;
            *(__nv_bfloat162*)(sm + OFF_BL + bo + 4) = l1;
        }
    };

    float Cf[4][4][4];
#pragma unroll
    for (int mi = 0; mi < 4; mi++)
#pragma unroll
        for (int nf = 0; nf < 4; nf++)
#pragma unroll
            for (int j = 0; j < 4; j++) Cf[mi][nf][j] = 0.0f;

    ld_chunk(0);
    st_chunk(0);
    __syncthreads();

    const uint32_t a_r  = (uint32_t)(wr * 64 + (lane & 7) + ((lane >> 3) & 1) * 8);
    const uint32_t a_cb = (uint32_t)((lane >> 4) * 16);
    const uint32_t b_r  = (uint32_t)(((lane >> 3) & 1) * 8 + (lane & 7));
    const uint32_t b_cb = (uint32_t)((wc * 32 + ((lane >> 4) & 1) * 8) * 2);

    for (int c = 0; c < NCHUNK; c++) {
        if (c + 1 < NCHUNK) ld_chunk((c + 1) * BKg);
        const int buf = c & 1;
        const uint32_t abase = smb + buf * A_BUF;
        const uint32_t bbase = smb + buf * B_BUF;

#pragma unroll
        for (int ks = 0; ks < BKg; ks += 16) {
            uint32_t ah[4][4], al[4][4], bh[4][2], bl[4][2];
#pragma unroll
            for (int mi = 0; mi < 4; mi++) {
                const uint32_t ao = (a_r + mi * 16) * A_PITCH + ks * 2 + a_cb;
                ldsm4(abase + OFF_AH + ao, ah[mi]);
                ldsm4(abase + OFF_AL + ao, al[mi]);
            }
#pragma unroll
            for (int half = 0; half < 2; half++) {
                const uint32_t bo = (ks + b_r) * B_PITCH + b_cb + half * 32;
                uint32_t t4[4];
                ldsm4t(bbase + OFF_BH + bo, t4);
                bh[half * 2][0] = t4[0]; bh[half * 2][1] = t4[1];
                bh[half * 2 + 1][0] = t4[2]; bh[half * 2 + 1][1] = t4[3];
                ldsm4t(bbase + OFF_BL + bo, t4);
                bl[half * 2][0] = t4[0]; bl[half * 2][1] = t4[1];
                bl[half * 2 + 1][0] = t4[2]; bl[half * 2 + 1][1] = t4[3];
            }
#pragma unroll
            for (int mi = 0; mi < 4; mi++)
#pragma unroll
                for (int nf = 0; nf < 4; nf++) {
                    mma16816(Cf[mi][nf], ah[mi], bh[nf]);
                    mma16816(Cf[mi][nf], al[mi], bh[nf]);
                    mma16816(Cf[mi][nf], ah[mi], bl[nf]);
                }
        }
        if (c + 1 < NCHUNK) st_chunk(1 - buf);
        __syncthreads();
    }

#pragma unroll
    for (int mi = 0; mi < 4; mi++) {
        const int rg = row0 + wr * 64 + mi * 16 + (lane >> 2);
#pragma unroll
        for (int nf = 0; nf < 4; nf++) {
            const int cg = col0 + wc * 32 + nf * 8 + (lane & 3) * 2;
            float2 v0 = make_float2(Cf[mi][nf][0] * scale, Cf[mi][nf][1] * scale);
            float2 v1 = make_float2(Cf[mi][nf][2] * scale, Cf[mi][nf][3] * scale);
            if (splitout) {
                const int h = cg >> 6, d = cg & 63;
                const int b0_ = rg >> 11, i0_ = rg & 2047;
                const int b1_ = (rg + 8) >> 11, i1_ = (rg + 8) & 2047;
                const size_t idx0 = (((size_t)(b0_ * Hc + h) * Ic + i0_) << 6) + d;
                const size_t idx1 = (((size_t)(b1_ * Hc + h) * Ic + i1_) << 6) + d;
                __nv_bfloat162 hh, ll;
                cvt_split(v0.x, v0.y, hh, ll);
                *(__nv_bfloat162*)(Ch + idx0) = hh;
                *(__nv_bfloat162*)(Cl + idx0) = ll;
                cvt_split(v1.x, v1.y, hh, ll);
                *(__nv_bfloat162*)(Ch + idx1) = hh;
                *(__nv_bfloat162*)(Cl + idx1) = ll;
            } else {
                *(float2*)&Cout[(size_t)rg * Dc + cg]       = v0;
                *(float2*)&Cout[(size_t)(rg + 8) * Dc + cg] = v1;
            }
        }
    }
}

__global__ __launch_bounds__(256) void qkv_kernel(
    const float* __restrict__ input, const float* __restrict__ memory,
    const float* __restrict__ Wq, const float* __restrict__ Wk,
    const float* __restrict__ Wv)
{
    if (blockIdx.z == 0)       gemm_sm(input,  Wq, nullptr, g_Qh, g_Ql, 0.125f, true);
    else if (blockIdx.z == 1)  gemm_sm(memory, Wk, nullptr, g_Kh, g_Kl, 1.0f,   true);
    else                       gemm_sm(memory, Wv, nullptr, g_Vh, g_Vl, 1.0f,   true);
}

__global__ __launch_bounds__(256) void out_kernel(
    const float* __restrict__ Wo, float* __restrict__ out)
{
    gemm_sm(g_O, Wo, out, nullptr, nullptr, 1.0f, false);
}

// ============== stats: S = Q K^T + bias -> online (m, 1/l) only =============
#define LP 144
#define LKBUF 9216
__global__ __launch_bounds__(256) void stats_kernel(
    const float* __restrict__ bias)
{
    __shared__ char sm[4 * LKBUF];
    const uint32_t smb = smem_u32(sm);
    const int tid = threadIdx.x, wid = tid >> 5, lane = tid & 31;
    const int bh = blockIdx.y, b = bh >> 4;
    const int i0 = blockIdx.x * 128;

#pragma unroll
    for (int t = 0; t < 4; t++) {
        const int fi = tid + t * 256;
        const int r = fi >> 3, c = fi & 7;
        const size_t gi = ((size_t)bh * Ic + i0 + r) * 64;
        *(uint4*)(sm + r * LP + c * 16)             = *((const uint4*)(g_Qh + gi) + c);
        *(uint4*)(sm + 2 * LKBUF + r * LP + c * 16) = *((const uint4*)(g_Ql + gi) + c);
    }
    __syncthreads();

    uint32_t qh[4][4], ql[4][4];
    const uint32_t a_off = (uint32_t)((wid * 16 + (lane & 7) + ((lane >> 3) & 1) * 8) * LP
                                      + (lane >> 4) * 16);
#pragma unroll
    for (int ks = 0; ks < 4; ks++) {
        ldsm4(smb + a_off + ks * 32, qh[ks]);
        ldsm4(smb + 2 * LKBUF + a_off + ks * 32, ql[ks]);
    }
    __syncthreads();

    // cp.async K staging, double-buffered
    auto stageK = [&](int m0, int base) {
#pragma unroll
        for (int t = 0; t < 4; t++) {
            const int fi = tid + t * 256;        // 0..1023
            const int r = (fi >> 3) & 63, c = fi & 7;
            const __nv_bfloat16* src = (t < 2 ? g_Kh : g_Kl);
            const int off = (t < 2 ? 0 : LKBUF);
            cp16(smb + base + off + r * LP + c * 16,
                 src + ((size_t)bh * Mc + m0 + r) * 64 + c * 8);
        }
    };
    stageK(0, 0);
    CP_COMMIT();
    CP_WAIT0();
    __syncthreads();

    const int r0 = lane >> 2;
    float m_run[2] = {-3.402823466e38f, -3.402823466e38f};
    float l_run[2] = {0.0f, 0.0f};

    const uint32_t b_row = (uint32_t)((lane & 7) + (lane >> 4) * 8);
    const uint32_t b_kb  = (uint32_t)(((lane >> 3) & 1) * 16);

    for (int c = 0; c < 32; c++) {
        const int m0 = c * 64;
        const int buf = (c & 1) * 2 * LKBUF;
        if (c + 1 < 32) {
            stageK((c + 1) * 64, (1 - (c & 1)) * 2 * LKBUF);
            CP_COMMIT();
        }

        float Cf[8][4];
#pragma unroll
        for (int nf = 0; nf < 8; nf++)
#pragma unroll
            for (int j = 0; j < 4; j++) Cf[nf][j] = 0.0f;

#pragma unroll
        for (int ks = 0; ks < 4; ks++) {
            uint32_t kh[8][2], kl[8][2];
#pragma unroll
            for (int mg = 0; mg < 4; mg++) {
                const uint32_t baddr = smb + buf + (mg * 16 + b_row) * LP + ks * 32 + b_kb;
                uint32_t t4[4];
                ldsm4(baddr, t4);
                kh[mg * 2][0] = t4[0]; kh[mg * 2][1] = t4[1];
                kh[mg * 2 + 1][0] = t4[2]; kh[mg * 2 + 1][1] = t4[3];
                ldsm4(baddr + LKBUF, t4);
                kl[mg * 2][0] = t4[0]; kl[mg * 2][1] = t4[1];
                kl[mg * 2 + 1][0] = t4[2]; kl[mg * 2 + 1][1] = t4[3];
            }
#pragma unroll
            for (int nf = 0; nf < 8; nf++) {
                mma16816(Cf[nf], qh[ks], kh[nf]);
                mma16816(Cf[nf], ql[ks], kh[nf]);
                mma16816(Cf[nf], qh[ks], kl[nf]);
            }
        }

        float mx[2] = {-3.402823466e38f, -3.402823466e38f};
#pragma unroll
        for (int nf = 0; nf < 8; nf++) {
            const int col = m0 + nf * 8 + (lane & 3) * 2;
#pragma unroll
            for (int rr = 0; rr < 2; rr++) {
                const int irow = i0 + wid * 16 + r0 + rr * 8;
                const float2 bv = *(const float2*)(bias + ((size_t)(b * Ic) + irow) * Mc + col);
                float s0 = Cf[nf][rr * 2 + 0] + bv.x;
                float s1 = Cf[nf][rr * 2 + 1] + bv.y;
                Cf[nf][rr * 2 + 0] = s0; Cf[nf][rr * 2 + 1] = s1;
                mx[rr] = fmaxf(mx[rr], fmaxf(s0, s1));
            }
        }
#pragma unroll
        for (int rr = 0; rr < 2; rr++) {
            mx[rr] = fmaxf(mx[rr], __shfl_xor_sync(0xffffffffu, mx[rr], 1));
            mx[rr] = fmaxf(mx[rr], __shfl_xor_sync(0xffffffffu, mx[rr], 2));
            const float mnew = fmaxf(m_run[rr], mx[rr]);
            const float sc = fexp(m_run[rr] - mnew);
            float ps = 0.0f;
#pragma unroll
            for (int nf = 0; nf < 8; nf++)
                ps += fexp(Cf[nf][rr * 2] - mnew) + fexp(Cf[nf][rr * 2 + 1] - mnew);
            ps += __shfl_xor_sync(0xffffffffu, ps, 1);
            ps += __shfl_xor_sync(0xffffffffu, ps, 2);
            l_run[rr] = l_run[rr] * sc + ps;
            m_run[rr] = mnew;
        }

        if (c + 1 < 32) {
            CP_WAIT0();
            __syncthreads();
        }
    }

    if ((lane & 3) == 0) {
#pragma unroll
        for (int rr = 0; rr < 2; rr++) {
            const int irow = i0 + wid * 16 + r0 + rr * 8;
            g_stats[bh * Ic + irow] = make_float2(m_run[rr], 1.0f / l_run[rr]);
        }
    }
}

// ==== spv: recompute S, p = exp(s-m)/l -> align (final), O += P V (fused) ===
// P never touches smem: S accumulator frags are re-packed in registers as the
// A operand of the PV MMA (C m16n8 frag layout == A m16k16 frag layout).
#define SPV_ARR  9216            // one 64x64 bf16 array at pitch 144
#define SPV_BUF  (4 * SPV_ARR)   // Kh, Kl, Vh, Vl
#define SMEM_SPV (2 * SPV_BUF)   // 73728 (double buffer)
__global__ __launch_bounds__(256) void spv_kernel(
    const float* __restrict__ bias, float* __restrict__ align)
{
    extern __shared__ char smp[];
    const uint32_t smb = smem_u32(smp);
    const int tid = threadIdx.x, wid = tid >> 5, lane = tid & 31;
    const int bh = blockIdx.y, b = bh >> 4, h = bh & 15;
    const int i0 = blockIdx.x * 128;

    // ---- stage Q into buf0 region, extract frags ----
#pragma unroll
    for (int t = 0; t < 4; t++) {
        const int fi = tid + t * 256;
        const int r = fi >> 3, c = fi & 7;
        const size_t gi = ((size_t)bh * Ic + i0 + r) * 64;
        *(uint4*)(smp + r * LP + c * 16)           = *((const uint4*)(g_Qh + gi) + c);
        *(uint4*)(smp + 2 * SPV_ARR + r * LP + c * 16) = *((const uint4*)(g_Ql + gi) + c);
    }
    __syncthreads();
    uint32_t qh[4][4], ql[4][4];
    const uint32_t a_off = (uint32_t)((wid * 16 + (lane & 7) + ((lane >> 3) & 1) * 8) * LP
                                      + (lane >> 4) * 16);
#pragma unroll
    for (int ks = 0; ks < 4; ks++) {
        ldsm4(smb + a_off + ks * 32, qh[ks]);
        ldsm4(smb + 2 * SPV_ARR + a_off + ks * 32, ql[ks]);
    }
    __syncthreads();

    const int r0 = lane >> 2;
    const int irow0 = i0 + wid * 16 + r0;
    const float2 st0 = g_stats[bh * Ic + irow0];
    const float2 st1 = g_stats[bh * Ic + irow0 + 8];

    // ---- K/V cp.async staging ----
    auto stageKV = [&](int m0, int base) {
        const __nv_bfloat16* srcs[4] = {g_Kh, g_Kl, g_Vh, g_Vl};
#pragma unroll
        for (int t = 0; t < 8; t++) {
            const int fi = tid + t * 256;          // 0..2047
            const int arr = t >> 1;
            const int w = fi & 511;
            const int r = w >> 3, c = w & 7;
            cp16(smb + base + arr * SPV_ARR + r * LP + c * 16,
                 srcs[arr] + ((size_t)bh * Mc + m0 + r) * 64 + c * 8);
        }
    };
    stageKV(0, 0);
    CP_COMMIT();
    CP_WAIT0();
    __syncthreads();

    float Oacc[8][4];
#pragma unroll
    for (int nf = 0; nf < 8; nf++)
#pragma unroll
        for (int j = 0; j < 4; j++) Oacc[nf][j] = 0.0f;

    const uint32_t b_row = (uint32_t)((lane & 7) + (lane >> 4) * 8);
    const uint32_t b_kb  = (uint32_t)(((lane >> 3) & 1) * 16);
    const uint32_t vb_r  = (uint32_t)(((lane >> 3) & 1) * 8 + (lane & 7));
    const uint32_t vb_c  = (uint32_t)(((lane >> 4) & 1) * 16);

    for (int c = 0; c < 32; c++) {
        const int m0 = c * 64;
        const uint32_t buf = (uint32_t)((c & 1) * SPV_BUF);
        if (c + 1 < 32) {
            stageKV((c + 1) * 64, (1 - (c & 1)) * SPV_BUF);
            CP_COMMIT();
        }

        // ---- S = Q K^T (3-term) ----
        float Cf[8][4];
#pragma unroll
        for (int nf = 0; nf < 8; nf++)
#pragma unroll
            for (int j = 0; j < 4; j++) Cf[nf][j] = 0.0f;
#pragma unroll
        for (int ks = 0; ks < 4; ks++) {
            uint32_t kh[8][2], kl[8][2];
#pragma unroll
            for (int mg = 0; mg < 4; mg++) {
                const uint32_t baddr = smb + buf + (mg * 16 + b_row) * LP + ks * 32 + b_kb;
                uint32_t t4[4];
                ldsm4(baddr, t4);
                kh[mg * 2][0] = t4[0]; kh[mg * 2][1] = t4[1];
                kh[mg * 2 + 1][0] = t4[2]; kh[mg * 2 + 1][1] = t4[3];
                ldsm4(baddr + SPV_ARR, t4);
                kl[mg * 2][0] = t4[0]; kl[mg * 2][1] = t4[1];
                kl[mg * 2 + 1][0] = t4[2]; kl[mg * 2 + 1][1] = t4[3];
            }
#pragma unroll
            for (int nf = 0; nf < 8; nf++) {
                mma16816(Cf[nf], qh[ks], kh[nf]);
                mma16816(Cf[nf], ql[ks], kh[nf]);
                mma16816(Cf[nf], qh[ks], kl[nf]);
            }
        }

        // ---- p = exp(s + bias - m) * invl; write final align; keep p in Cf ----
#pragma unroll
        for (int nf = 0; nf < 8; nf++) {
            const int col = m0 + nf * 8 + (lane & 3) * 2;
            const float2 bv0 = *(const float2*)(bias + ((size_t)(b * Ic) + irow0) * Mc + col);
            const float2 bv1 = *(const float2*)(bias + ((size_t)(b * Ic) + irow0 + 8) * Mc + col);
            float p0 = fexp(Cf[nf][0] + bv0.x - st0.x) * st0.y;
            float p1 = fexp(Cf[nf][1] + bv0.y - st0.x) * st0.y;
            float p2 = fexp(Cf[nf][2] + bv1.x - st1.x) * st1.y;
            float p3 = fexp(Cf[nf][3] + bv1.y - st1.x) * st1.y;
            Cf[nf][0] = p0; Cf[nf][1] = p1; Cf[nf][2] = p2; Cf[nf][3] = p3;
            *(float2*)(align + ((size_t)(bh * Ic) + irow0) * Mc + col)     = make_float2(p0, p1);
            *(float2*)(align + ((size_t)(bh * Ic) + irow0 + 8) * Mc + col) = make_float2(p2, p3);
        }

        // ---- O += P V: re-pack C frags as A frags, V from smem ----
#pragma unroll
        for (int kk = 0; kk < 4; kk++) {
            uint32_t ah[4], al[4];
            __nv_bfloat162 hh, ll;
            cvt_split(Cf[2 * kk][0], Cf[2 * kk][1], hh, ll);
            ah[0] = *(uint32_t*)&hh; al[0] = *(uint32_t*)&ll;
            cvt_split(Cf[2 * kk][2], Cf[2 * kk][3], hh, ll);
            ah[1] = *(uint32_t*)&hh; al[1] = *(uint32_t*)&ll;
            cvt_split(Cf[2 * kk + 1][0], Cf[2 * kk + 1][1], hh, ll);
            ah[2] = *(uint32_t*)&hh; al[2] = *(uint32_t*)&ll;
            cvt_split(Cf[2 * kk + 1][2], Cf[2 * kk + 1][3], hh, ll);
            ah[3] = *(uint32_t*)&hh; al[3] = *(uint32_t*)&ll;

            uint32_t vh[8][2], vl[8][2];
#pragma unroll
            for (int q = 0; q < 4; q++) {
                const uint32_t vaddr = smb + buf + 2 * SPV_ARR
                                       + (kk * 16 + vb_r) * LP + q * 32 + vb_c;
                uint32_t t4[4];
                ldsm4t(vaddr, t4);
                vh[q * 2][0] = t4[0]; vh[q * 2][1] = t4[1];
                vh[q * 2 + 1][0] = t4[2]; vh[q * 2 + 1][1] = t4[3];
                ldsm4t(vaddr + SPV_ARR, t4);
                vl[q * 2][0] = t4[0]; vl[q * 2][1] = t4[1];
                vl[q * 2 + 1][0] = t4[2]; vl[q * 2 + 1][1] = t4[3];
            }
#pragma unroll
            for (int nf = 0; nf < 8; nf++) {
                mma16816(Oacc[nf], ah, vh[nf]);
                mma16816(Oacc[nf], al, vh[nf]);
                mma16816(Oacc[nf], ah, vl[nf]);
            }
        }

        if (c + 1 < 32) {
            CP_WAIT0();
            __syncthreads();
        }
    }

    // ---- epilogue: O -> g_O fp32 [b][i][h*64+d] ----
#pragma unroll
    for (int nf = 0; nf < 8; nf++) {
        const int d = nf * 8 + (lane & 3) * 2;
        *(float2*)(g_O + ((size_t)(b * Ic) + irow0) * Dc + h * 64 + d) =
            make_float2(Oacc[nf][0], Oacc[nf][1]);
        *(float2*)(g_O + ((size_t)(b * Ic) + irow0 + 8) * Dc + h * 64 + d) =
            make_float2(Oacc[nf][2], Oacc[nf][3]);
    }
}

// ---------------- launch ----------------------------------------------------
extern "C" void kernel_launch(void* const* d_in, const int* in_sizes, int n_in,
                              void* d_out, int out_size)
{
    const float* input  = (const float*)d_in[0];
    const float* memory = (const float*)d_in[1];
    const float* bias   = (const float*)d_in[2];
    const float* Wq     = (const float*)d_in[3];
    const float* Wk     = (const float*)d_in[4];
    const float* Wv     = (const float*)d_in[5];
    const float* Wo     = (const float*)d_in[6];

    float* out   = (float*)d_out;                  // [B,I,D]
    float* align = out + (size_t)Bc * Ic * Dc;     // [B,H,I,M]

    static int attr_done = 0;
    if (!attr_done) {
        cudaFuncSetAttribute(qkv_kernel, cudaFuncAttributeMaxDynamicSharedMemorySize, SMEM_GEMM);
        cudaFuncSetAttribute(out_kernel, cudaFuncAttributeMaxDynamicSharedMemorySize, SMEM_GEMM);
        cudaFuncSetAttribute(spv_kernel, cudaFuncAttributeMaxDynamicSharedMemorySize, SMEM_SPV);
        attr_done = 1;
    }

    dim3 gqkv(Dc / 128, (Bc * Ic) / 128, 3);       // (8, 32, 3)
    qkv_kernel<<<gqkv, 256, SMEM_GEMM>>>(input, memory, Wq, Wk, Wv);

    stats_kernel<<<dim3(Ic / 128, BHc), 256>>>(bias);

    spv_kernel<<<dim3(Ic / 128, BHc), 256, SMEM_SPV>>>(bias, align);

    out_kernel<<<dim3(Dc / 128, (Bc * Ic) / 128), 256, SMEM_GEMM>>>(Wo, out);
}

// round 6
// speedup vs baseline: 1.1680x; 1.1680x over previous
#include <cuda_runtime.h>
#include <cuda_bf16.h>
#include <cuda_fp16.h>
#include <math.h>
#include <stdint.h>

#define Bc  2
#define Ic  2048
#define Mc  2048
#define Dc  1024
#define Hc  16
#define Dhc 64
#define BHc 32   // Bc*Hc

// ---------------- scratch (static device globals; no allocs) ----------------
__device__ __nv_bfloat16 g_Qh[BHc * (size_t)Ic * Dhc];
__device__ __nv_bfloat16 g_Ql[BHc * (size_t)Ic * Dhc];
__device__ __nv_bfloat16 g_Kh[BHc * (size_t)Mc * Dhc];
__device__ __nv_bfloat16 g_Kl[BHc * (size_t)Mc * Dhc];
__device__ __nv_bfloat16 g_Vh[BHc * (size_t)Mc * Dhc];
__device__ __nv_bfloat16 g_Vl[BHc * (size_t)Mc * Dhc];
__device__ float  g_O[Bc * (size_t)Ic * Dc];     // [B,I,D] (pre-Wo)
__device__ float2 g_stats[BHc * Ic];             // (rowmax, 1/rowsum)
__device__ __half g_E[BHc * (size_t)Ic * Mc];    // e = exp(s - m_tile), fp16
__device__ float  g_mt[BHc * 32 * (size_t)Ic];   // per (bh, m-tile, row) local max

// ======================= mma.sync helpers (sm_80+ path) =====================
__device__ __forceinline__ uint32_t smem_u32(const void* p) {
    return (uint32_t)__cvta_generic_to_shared(p);
}
__device__ __forceinline__ void ldsm4(uint32_t addr, uint32_t* r) {
    asm volatile("ldmatrix.sync.aligned.m8n8.x4.shared.b16 {%0,%1,%2,%3}, [%4];"
                 : "=r"(r[0]), "=r"(r[1]), "=r"(r[2]), "=r"(r[3]) : "r"(addr));
}
__device__ __forceinline__ void ldsm4t(uint32_t addr, uint32_t* r) {
    asm volatile("ldmatrix.sync.aligned.m8n8.x4.trans.shared.b16 {%0,%1,%2,%3}, [%4];"
                 : "=r"(r[0]), "=r"(r[1]), "=r"(r[2]), "=r"(r[3]) : "r"(addr));
}
__device__ __forceinline__ void mma16816(float* c, const uint32_t* a, const uint32_t* b) {
    asm volatile(
        "mma.sync.aligned.m16n8k16.row.col.f32.bf16.bf16.f32 "
        "{%0,%1,%2,%3}, {%4,%5,%6,%7}, {%8,%9}, {%0,%1,%2,%3};"
        : "+f"(c[0]), "+f"(c[1]), "+f"(c[2]), "+f"(c[3])
        : "r"(a[0]), "r"(a[1]), "r"(a[2]), "r"(a[3]), "r"(b[0]), "r"(b[1]));
}
__device__ __forceinline__ void cvt_split(float x, float y,
                                          __nv_bfloat162& h, __nv_bfloat162& l) {
    __nv_bfloat16 hx = __float2bfloat16(x);
    __nv_bfloat16 hy = __float2bfloat16(y);
    h.x = hx; h.y = hy;
    l.x = __float2bfloat16(x - __bfloat162float(hx));
    l.y = __float2bfloat16(y - __bfloat162float(hy));
}
// fast exp on the FMA pipe (no MUFU)
__device__ __forceinline__ float fexp(float x) {
    float y = fmaxf(x * 1.4426950408889634f, -126.0f);
    float z = y + 12582912.0f;
    int   n = __float_as_int(z) - 0x4B400000;
    float r = y - (z - 12582912.0f);
    float w = r * 0.69314718055994531f;
    float p = fmaf(w, 1.3888889e-3f, 8.3333333e-3f);
    p = fmaf(w, p, 4.1666667e-2f);
    p = fmaf(w, p, 1.6666667e-1f);
    p = fmaf(w, p, 0.5f);
    p = fmaf(w, p, 1.0f);
    p = fmaf(w, p, 1.0f);
    return p * __int_as_float((n + 127) << 23);
}
__device__ __forceinline__ void cp16(uint32_t dst, const void* src) {
    asm volatile("cp.async.ca.shared.global [%0], [%1], 16;" :: "r"(dst), "l"(src));
}
#define CP_COMMIT() asm volatile("cp.async.commit_group;" ::: "memory")
#define CP_WAIT0()  asm volatile("cp.async.wait_group 0;" ::: "memory")

// ============ bf16-split tensor-core GEMM: C[4096x1024] = A @ W =============
#define BKg     32
#define NCHUNK  (Dc / BKg)          // 32
#define A_PITCH 80
#define B_PITCH 272
#define A_BUF   (128 * A_PITCH)
#define B_BUF   (BKg * B_PITCH)
#define OFF_AH  0
#define OFF_AL  (2 * A_BUF)
#define OFF_BH  (4 * A_BUF)
#define OFF_BL  (OFF_BH + 2 * B_BUF)
#define SMEM_GEMM (OFF_BL + 2 * B_BUF) // 75776

__device__ __forceinline__ void gemm_sm(const float* __restrict__ A,
                                        const float* __restrict__ W,
                                        float* __restrict__ Cout,
                                        __nv_bfloat16* __restrict__ Ch,
                                        __nv_bfloat16* __restrict__ Cl,
                                        float scale, bool splitout) {
    extern __shared__ char sm[];
    const uint32_t smb = smem_u32(sm);

    const int tid  = threadIdx.x;
    const int wid  = tid >> 5;
    const int lane = tid & 31;
    const int wr   = wid & 1;
    const int wc   = wid >> 1;
    const int row0 = blockIdx.y * 128;
    const int col0 = blockIdx.x * 128;

    int arow[4], ac4[4], wrow[4], wc4[4];
#pragma unroll
    for (int t = 0; t < 4; t++) {
        const int fi = tid + t * 256;
        arow[t] = fi >> 3;  ac4[t] = (fi & 7) * 4;
        wrow[t] = fi >> 5;  wc4[t] = (fi & 31) * 4;
    }

    float4 ra[4], rw[4];
    auto ld_chunk = [&](int k0) {
#pragma unroll
        for (int t = 0; t < 4; t++) {
            ra[t] = *(const float4*)(A + (size_t)(row0 + arow[t]) * Dc + k0 + ac4[t]);
            rw[t] = *(const float4*)(W + (size_t)(k0 + wrow[t]) * Dc + col0 + wc4[t]);
        }
    };
    auto st_chunk = [&](int buf) {
#pragma unroll
        for (int t = 0; t < 4; t++) {
            __nv_bfloat162 h0, l0, h1, l1;
            cvt_split(ra[t].x, ra[t].y, h0, l0);
            cvt_split(ra[t].z, ra[t].w, h1, l1);
            const int ao = buf * A_BUF + arow[t] * A_PITCH + ac4[t] * 2;
            *(__nv_bfloat162*)(sm + OFF_AH + ao)     = h0;
            *(__nv_bfloat162*)(sm + OFF_AH + ao + 4) = h1;
            *(__nv_bfloat162*)(sm + OFF_AL + ao)     = l0;
            *(__nv_bfloat162*)(sm + OFF_AL + ao + 4) = l1;
            cvt_split(rw[t].x, rw[t].y, h0, l0);
            cvt_split(rw[t].z, rw[t].w, h1, l1);
            const int bo = buf * B_BUF + wrow[t] * B_PITCH + wc4[t] * 2;
            *(__nv_bfloat162*)(sm + OFF_BH + bo)     = h0;
            *(__nv_bfloat162*)(sm + OFF_BH + bo + 4) = h1;
            *(__nv_bfloat162*)(sm + OFF_BL + bo)     = l0;
            *(__nv_bfloat162*)(sm + OFF_BL + bo + 4) = l1;
        }
    };

    float Cf[4][4][4];
#pragma unroll
    for (int mi = 0; mi < 4; mi++)
#pragma unroll
        for (int nf = 0; nf < 4; nf++)
#pragma unroll
            for (int j = 0; j < 4; j++) Cf[mi][nf][j] = 0.0f;

    ld_chunk(0);
    st_chunk(0);
    __syncthreads();

    const uint32_t a_r  = (uint32_t)(wr * 64 + (lane & 7) + ((lane >> 3) & 1) * 8);
    const uint32_t a_cb = (uint32_t)((lane >> 4) * 16);
    const uint32_t b_r  = (uint32_t)(((lane >> 3) & 1) * 8 + (lane & 7));
    const uint32_t b_cb = (uint32_t)((wc * 32 + ((lane >> 4) & 1) * 8) * 2);

    for (int c = 0; c < NCHUNK; c++) {
        if (c + 1 < NCHUNK) ld_chunk((c + 1) * BKg);
        const int buf = c & 1;
        const uint32_t abase = smb + buf * A_BUF;
        const uint32_t bbase = smb + buf * B_BUF;

#pragma unroll
        for (int ks = 0; ks < BKg; ks += 16) {
            uint32_t ah[4][4], al[4][4], bh[4][2], bl[4][2];
#pragma unroll
            for (int mi = 0; mi < 4; mi++) {
                const uint32_t ao = (a_r + mi * 16) * A_PITCH + ks * 2 + a_cb;
                ldsm4(abase + OFF_AH + ao, ah[mi]);
                ldsm4(abase + OFF_AL + ao, al[mi]);
            }
#pragma unroll
            for (int half = 0; half < 2; half++) {
                const uint32_t bo = (ks + b_r) * B_PITCH + b_cb + half * 32;
                uint32_t t4[4];
                ldsm4t(bbase + OFF_BH + bo, t4);
                bh[half * 2][0] = t4[0]; bh[half * 2][1] = t4[1];
                bh[half * 2 + 1][0] = t4[2]; bh[half * 2 + 1][1] = t4[3];
                ldsm4t(bbase + OFF_BL + bo, t4);
                bl[half * 2][0] = t4[0]; bl[half * 2][1] = t4[1];
                bl[half * 2 + 1][0] = t4[2]; bl[half * 2 + 1][1] = t4[3];
            }
#pragma unroll
            for (int mi = 0; mi < 4; mi++)
#pragma unroll
                for (int nf = 0; nf < 4; nf++) {
                    mma16816(Cf[mi][nf], ah[mi], bh[nf]);
                    mma16816(Cf[mi][nf], al[mi], bh[nf]);
                    mma16816(Cf[mi][nf], ah[mi], bl[nf]);
                }
        }
        if (c + 1 < NCHUNK) st_chunk(1 - buf);
        __syncthreads();
    }

#pragma unroll
    for (int mi = 0; mi < 4; mi++) {
        const int rg = row0 + wr * 64 + mi * 16 + (lane >> 2);
#pragma unroll
        for (int nf = 0; nf < 4; nf++) {
            const int cg = col0 + wc * 32 + nf * 8 + (lane & 3) * 2;
            float2 v0 = make_float2(Cf[mi][nf][0] * scale, Cf[mi][nf][1] * scale);
            float2 v1 = make_float2(Cf[mi][nf][2] * scale, Cf[mi][nf][3] * scale);
            if (splitout) {
                const int h = cg >> 6, d = cg & 63;
                const int b0_ = rg >> 11, i0_ = rg & 2047;
                const int b1_ = (rg + 8) >> 11, i1_ = (rg + 8) & 2047;
                const size_t idx0 = (((size_t)(b0_ * Hc + h) * Ic + i0_) << 6) + d;
                const size_t idx1 = (((size_t)(b1_ * Hc + h) * Ic + i1_) << 6) + d;
                __nv_bfloat162 hh, ll;
                cvt_split(v0.x, v0.y, hh, ll);
                *(__nv_bfloat162*)(Ch + idx0) = hh;
                *(__nv_bfloat162*)(Cl + idx0) = ll;
                cvt_split(v1.x, v1.y, hh, ll);
                *(__nv_bfloat162*)(Ch + idx1) = hh;
                *(__nv_bfloat162*)(Cl + idx1) = ll;
            } else {
                *(float2*)&Cout[(size_t)rg * Dc + cg]       = v0;
                *(float2*)&Cout[(size_t)(rg + 8) * Dc + cg] = v1;
            }
        }
    }
}

__global__ __launch_bounds__(256) void qkv_kernel(
    const float* __restrict__ input, const float* __restrict__ memory,
    const float* __restrict__ Wq, const float* __restrict__ Wk,
    const float* __restrict__ Wv)
{
    if (blockIdx.z == 0)       gemm_sm(input,  Wq, nullptr, g_Qh, g_Ql, 0.125f, true);
    else if (blockIdx.z == 1)  gemm_sm(memory, Wk, nullptr, g_Kh, g_Kl, 1.0f,   true);
    else                       gemm_sm(memory, Wv, nullptr, g_Vh, g_Vl, 1.0f,   true);
}

__global__ __launch_bounds__(256) void out_kernel(
    const float* __restrict__ Wo, float* __restrict__ out)
{
    gemm_sm(g_O, Wo, out, nullptr, nullptr, 1.0f, false);
}

// ===== pass 1: S = Q K^T + bias -> e=exp(s-m_tile) fp16, m_tile, (m, 1/l) ===
#define LP 144
#define LKBUF 9216
__global__ __launch_bounds__(256) void se_kernel(
    const float* __restrict__ bias)
{
    __shared__ char sm[4 * LKBUF];
    const uint32_t smb = smem_u32(sm);
    const int tid = threadIdx.x, wid = tid >> 5, lane = tid & 31;
    const int bh = blockIdx.y, b = bh >> 4;
    const int i0 = blockIdx.x * 128;

#pragma unroll
    for (int t = 0; t < 4; t++) {
        const int fi = tid + t * 256;
        const int r = fi >> 3, c = fi & 7;
        const size_t gi = ((size_t)bh * Ic + i0 + r) * 64;
        *(uint4*)(sm + r * LP + c * 16)             = *((const uint4*)(g_Qh + gi) + c);
        *(uint4*)(sm + 2 * LKBUF + r * LP + c * 16) = *((const uint4*)(g_Ql + gi) + c);
    }
    __syncthreads();

    uint32_t qh[4][4], ql[4][4];
    const uint32_t a_off = (uint32_t)((wid * 16 + (lane & 7) + ((lane >> 3) & 1) * 8) * LP
                                      + (lane >> 4) * 16);
#pragma unroll
    for (int ks = 0; ks < 4; ks++) {
        ldsm4(smb + a_off + ks * 32, qh[ks]);
        ldsm4(smb + 2 * LKBUF + a_off + ks * 32, ql[ks]);
    }
    __syncthreads();

    auto stageK = [&](int m0, int base) {
#pragma unroll
        for (int t = 0; t < 4; t++) {
            const int fi = tid + t * 256;
            const int r = (fi >> 3) & 63, c = fi & 7;
            const __nv_bfloat16* src = (t < 2 ? g_Kh : g_Kl);
            const int off = (t < 2 ? 0 : LKBUF);
            cp16(smb + base + off + r * LP + c * 16,
                 src + ((size_t)bh * Mc + m0 + r) * 64 + c * 8);
        }
    };
    stageK(0, 0);
    CP_COMMIT();
    CP_WAIT0();
    __syncthreads();

    const int r0 = lane >> 2;
    const int irow0 = i0 + wid * 16 + r0;
    float m_run[2] = {-3.402823466e38f, -3.402823466e38f};
    float l_run[2] = {0.0f, 0.0f};

    const uint32_t b_row = (uint32_t)((lane & 7) + (lane >> 4) * 8);
    const uint32_t b_kb  = (uint32_t)(((lane >> 3) & 1) * 16);

    for (int c = 0; c < 32; c++) {
        const int m0 = c * 64;
        const int buf = (c & 1) * 2 * LKBUF;
        if (c + 1 < 32) {
            stageK((c + 1) * 64, (1 - (c & 1)) * 2 * LKBUF);
            CP_COMMIT();
        }

        float Cf[8][4];
#pragma unroll
        for (int nf = 0; nf < 8; nf++)
#pragma unroll
            for (int j = 0; j < 4; j++) Cf[nf][j] = 0.0f;

#pragma unroll
        for (int ks = 0; ks < 4; ks++) {
            uint32_t kh[8][2], kl[8][2];
#pragma unroll
            for (int mg = 0; mg < 4; mg++) {
                const uint32_t baddr = smb + buf + (mg * 16 + b_row) * LP + ks * 32 + b_kb;
                uint32_t t4[4];
                ldsm4(baddr, t4);
                kh[mg * 2][0] = t4[0]; kh[mg * 2][1] = t4[1];
                kh[mg * 2 + 1][0] = t4[2]; kh[mg * 2 + 1][1] = t4[3];
                ldsm4(baddr + LKBUF, t4);
                kl[mg * 2][0] = t4[0]; kl[mg * 2][1] = t4[1];
                kl[mg * 2 + 1][0] = t4[2]; kl[mg * 2 + 1][1] = t4[3];
            }
#pragma unroll
            for (int nf = 0; nf < 8; nf++) {
                mma16816(Cf[nf], qh[ks], kh[nf]);
                mma16816(Cf[nf], ql[ks], kh[nf]);
                mma16816(Cf[nf], qh[ks], kl[nf]);
            }
        }

        // bias add + tile-local max
        float mx[2] = {-3.402823466e38f, -3.402823466e38f};
#pragma unroll
        for (int nf = 0; nf < 8; nf++) {
            const int col = m0 + nf * 8 + (lane & 3) * 2;
            const float2 bv0 = *(const float2*)(bias + ((size_t)(b * Ic) + irow0) * Mc + col);
            const float2 bv1 = *(const float2*)(bias + ((size_t)(b * Ic) + irow0 + 8) * Mc + col);
            Cf[nf][0] += bv0.x; Cf[nf][1] += bv0.y;
            Cf[nf][2] += bv1.x; Cf[nf][3] += bv1.y;
            mx[0] = fmaxf(mx[0], fmaxf(Cf[nf][0], Cf[nf][1]));
            mx[1] = fmaxf(mx[1], fmaxf(Cf[nf][2], Cf[nf][3]));
        }
#pragma unroll
        for (int rr = 0; rr < 2; rr++) {
            mx[rr] = fmaxf(mx[rr], __shfl_xor_sync(0xffffffffu, mx[rr], 1));
            mx[rr] = fmaxf(mx[rr], __shfl_xor_sync(0xffffffffu, mx[rr], 2));
        }

        // e = exp(s - mx_tile); store fp16; accumulate partial sums
        float ps[2] = {0.0f, 0.0f};
#pragma unroll
        for (int nf = 0; nf < 8; nf++) {
            const int col = m0 + nf * 8 + (lane & 3) * 2;
            float e0 = fexp(Cf[nf][0] - mx[0]);
            float e1 = fexp(Cf[nf][1] - mx[0]);
            float e2 = fexp(Cf[nf][2] - mx[1]);
            float e3 = fexp(Cf[nf][3] - mx[1]);
            ps[0] += e0 + e1;
            ps[1] += e2 + e3;
            *(__half2*)(g_E + ((size_t)(bh * Ic) + irow0) * Mc + col) =
                __floats2half2_rn(e0, e1);
            *(__half2*)(g_E + ((size_t)(bh * Ic) + irow0 + 8) * Mc + col) =
                __floats2half2_rn(e2, e3);
        }

#pragma unroll
        for (int rr = 0; rr < 2; rr++) {
            ps[rr] += __shfl_xor_sync(0xffffffffu, ps[rr], 1);
            ps[rr] += __shfl_xor_sync(0xffffffffu, ps[rr], 2);
            const float mnew = fmaxf(m_run[rr], mx[rr]);
            l_run[rr] = l_run[rr] * fexp(m_run[rr] - mnew) + ps[rr] * fexp(mx[rr] - mnew);
            m_run[rr] = mnew;
        }
        if ((lane & 3) == 0) {
            g_mt[((size_t)(bh * 32 + c)) * Ic + irow0]     = mx[0];
            g_mt[((size_t)(bh * 32 + c)) * Ic + irow0 + 8] = mx[1];
        }

        if (c + 1 < 32) {
            CP_WAIT0();
            __syncthreads();
        }
    }

    if ((lane & 3) == 0) {
#pragma unroll
        for (int rr = 0; rr < 2; rr++) {
            g_stats[bh * Ic + irow0 + rr * 8] = make_float2(m_run[rr], 1.0f / l_run[rr]);
        }
    }
}

// ===== pass 2: p = e * exp(m_tile - m)/l -> align (final); O = P V ==========
#define PVARR 9216             // one 64x64 bf16 array at pitch LP
#define PVB   (2 * PVARR)      // Vh, Vl
__global__ __launch_bounds__(256) void pv_kernel(float* __restrict__ align)
{
    __shared__ char smp[2 * PVB];     // 36864: double-buffered V
    const uint32_t smb = smem_u32(smp);
    const int tid = threadIdx.x, wid = tid >> 5, lane = tid & 31;
    const int bh = blockIdx.y, b = bh >> 4, h = bh & 15;
    const int i0 = blockIdx.x * 128;

    const int r0 = lane >> 2;
    const int irow0 = i0 + wid * 16 + r0;
    const float2 st0 = g_stats[bh * Ic + irow0];
    const float2 st1 = g_stats[bh * Ic + irow0 + 8];

    auto stageV = [&](int m0, int base) {
#pragma unroll
        for (int t = 0; t < 4; t++) {
            const int fi = tid + t * 256;        // 0..1023
            const int w = fi & 511;
            const int r = w >> 3, cc = w & 7;
            const __nv_bfloat16* src = (t < 2 ? g_Vh : g_Vl);
            const int off = (t < 2 ? 0 : PVARR);
            cp16(smb + base + off + r * LP + cc * 16,
                 src + ((size_t)bh * Mc + m0 + r) * 64 + cc * 8);
        }
    };
    stageV(0, 0);
    CP_COMMIT();
    CP_WAIT0();
    __syncthreads();

    float Oacc[8][4];
#pragma unroll
    for (int nf = 0; nf < 8; nf++)
#pragma unroll
        for (int j = 0; j < 4; j++) Oacc[nf][j] = 0.0f;

    const uint32_t vb_r = (uint32_t)(((lane >> 3) & 1) * 8 + (lane & 7));
    const uint32_t vb_c = (uint32_t)(((lane >> 4) & 1) * 16);

    for (int c = 0; c < 32; c++) {
        const int m0 = c * 64;
        const uint32_t buf = (uint32_t)((c & 1) * PVB);
        if (c + 1 < 32) {
            stageV((c + 1) * 64, (1 - (c & 1)) * PVB);
            CP_COMMIT();
        }

        // per-row scale for this tile
        const float sc0 = fexp(g_mt[((size_t)(bh * 32 + c)) * Ic + irow0]     - st0.x) * st0.y;
        const float sc1 = fexp(g_mt[((size_t)(bh * 32 + c)) * Ic + irow0 + 8] - st1.x) * st1.y;

        // p = e * scale; write final align; keep p in Cf
        float Cf[8][4];
#pragma unroll
        for (int nf = 0; nf < 8; nf++) {
            const int col = m0 + nf * 8 + (lane & 3) * 2;
            const __half2 ea = *(const __half2*)(g_E + ((size_t)(bh * Ic) + irow0) * Mc + col);
            const __half2 eb = *(const __half2*)(g_E + ((size_t)(bh * Ic) + irow0 + 8) * Mc + col);
            const float2 fa = __half22float2(ea);
            const float2 fb = __half22float2(eb);
            float p0 = fa.x * sc0, p1 = fa.y * sc0;
            float p2 = fb.x * sc1, p3 = fb.y * sc1;
            Cf[nf][0] = p0; Cf[nf][1] = p1; Cf[nf][2] = p2; Cf[nf][3] = p3;
            *(float2*)(align + ((size_t)(bh * Ic) + irow0) * Mc + col)     = make_float2(p0, p1);
            *(float2*)(align + ((size_t)(bh * Ic) + irow0 + 8) * Mc + col) = make_float2(p2, p3);
        }

        // O += P V: re-pack p frags as A frags (C-frag layout == A-frag layout)
#pragma unroll
        for (int kk = 0; kk < 4; kk++) {
            uint32_t ah[4], al[4];
            __nv_bfloat162 hh, ll;
            cvt_split(Cf[2 * kk][0], Cf[2 * kk][1], hh, ll);
            ah[0] = *(uint32_t*)&hh; al[0] = *(uint32_t*)&ll;
            cvt_split(Cf[2 * kk][2], Cf[2 * kk][3], hh, ll);
            ah[1] = *(uint32_t*)&hh; al[1] = *(uint32_t*)&ll;
            cvt_split(Cf[2 * kk + 1][0], Cf[2 * kk + 1][1], hh, ll);
            ah[2] = *(uint32_t*)&hh; al[2] = *(uint32_t*)&ll;
            cvt_split(Cf[2 * kk + 1][2], Cf[2 * kk + 1][3], hh, ll);
            ah[3] = *(uint32_t*)&hh; al[3] = *(uint32_t*)&ll;

            uint32_t vh[8][2], vl[8][2];
#pragma unroll
            for (int q = 0; q < 4; q++) {
                const uint32_t vaddr = smb + buf + (kk * 16 + vb_r) * LP + q * 32 + vb_c;
                uint32_t t4[4];
                ldsm4t(vaddr, t4);
                vh[q * 2][0] = t4[0]; vh[q * 2][1] = t4[1];
                vh[q * 2 + 1][0] = t4[2]; vh[q * 2 + 1][1] = t4[3];
                ldsm4t(vaddr + PVARR, t4);
                vl[q * 2][0] = t4[0]; vl[q * 2][1] = t4[1];
                vl[q * 2 + 1][0] = t4[2]; vl[q * 2 + 1][1] = t4[3];
            }
#pragma unroll
            for (int nf = 0; nf < 8; nf++) {
                mma16816(Oacc[nf], ah, vh[nf]);
                mma16816(Oacc[nf], al, vh[nf]);
                mma16816(Oacc[nf], ah, vl[nf]);
            }
        }

        if (c + 1 < 32) {
            CP_WAIT0();
            __syncthreads();
        }
    }

#pragma unroll
    for (int nf = 0; nf < 8; nf++) {
        const int d = nf * 8 + (lane & 3) * 2;
        *(float2*)(g_O + ((size_t)(b * Ic) + irow0) * Dc + h * 64 + d) =
            make_float2(Oacc[nf][0], Oacc[nf][1]);
        *(float2*)(g_O + ((size_t)(b * Ic) + irow0 + 8) * Dc + h * 64 + d) =
            make_float2(Oacc[nf][2], Oacc[nf][3]);
    }
}

// ---------------- launch ----------------------------------------------------
extern "C" void kernel_launch(void* const* d_in, const int* in_sizes, int n_in,
                              void* d_out, int out_size)
{
    const float* input  = (const float*)d_in[0];
    const float* memory = (const float*)d_in[1];
    const float* bias   = (const float*)d_in[2];
    const float* Wq     = (const float*)d_in[3];
    const float* Wk     = (const float*)d_in[4];
    const float* Wv     = (const float*)d_in[5];
    const float* Wo     = (const float*)d_in[6];

    float* out   = (float*)d_out;                  // [B,I,D]
    float* align = out + (size_t)Bc * Ic * Dc;     // [B,H,I,M]

    static int attr_done = 0;
    if (!attr_done) {
        cudaFuncSetAttribute(qkv_kernel, cudaFuncAttributeMaxDynamicSharedMemorySize, SMEM_GEMM);
        cudaFuncSetAttribute(out_kernel, cudaFuncAttributeMaxDynamicSharedMemorySize, SMEM_GEMM);
        attr_done = 1;
    }

    dim3 gqkv(Dc / 128, (Bc * Ic) / 128, 3);       // (8, 32, 3)
    qkv_kernel<<<gqkv, 256, SMEM_GEMM>>>(input, memory, Wq, Wk, Wv);

    se_kernel<<<dim3(Ic / 128, BHc), 256>>>(bias);

    pv_kernel<<<dim3(Ic / 128, BHc), 256>>>(align);

    out_kernel<<<dim3(Dc / 128, (Bc * Ic) / 128), 256, SMEM_GEMM>>>(Wo, out);
}